// round 14
// baseline (speedup 1.0000x reference)
#include <cuda_runtime.h>
#include <math.h>
#include <stdint.h>

#define Sd   2048
#define Hd   2048
#define NHd  16
#define Dd   128
#define Ed   8
#define IEd  1408
#define ISd  5632
#define QKVW 6144            // 3*Hd
#define GUW  2816            // 2*IEd
#define SGW  11264           // 2*ISd

// ---------------- static scratch ----------------
__device__ float g_h1[Sd * Hd];
__device__ float g_qkv[Sd * QKVW];
__device__ float g_attn[Sd * Hd];
__device__ float g_h2[Sd * Hd];
__device__ float g_h2x[Sd * Hd];
__device__ int   g_cnt[Ed];
__device__ int   g_idx[Ed * Sd];
__device__ float g_w4[Sd * 4];
__device__ int   g_sel4[Sd * 4];
__device__ int   g_pos4[Sd * 4];
__device__ float g_GU[(long long)Ed * Sd * GUW];
__device__ float g_Ye[(long long)Ed * Sd * Hd];
__device__ float g_SGU[(long long)Sd * SGW];
__device__ float g_Ysh[Sd * Hd];
__device__ float g_sig[Sd];
__device__ float g_bqkv[QKVW];
// transposed + tf32-rounded weights ([N,K])
__device__ float g_qkvT[(long long)QKVW * Hd];
__device__ float g_woT[Hd * Hd];
__device__ float g_guT[(long long)Ed * GUW * Hd];
__device__ float g_edT[(long long)Ed * Hd * IEd];
__device__ float g_sguT[(long long)SGW * Hd];
__device__ float g_sdT[(long long)Hd * ISd];

__device__ __forceinline__ uint32_t cvt_tf32(float f) {
    uint32_t r;
    asm("cvt.rna.tf32.f32 %0, %1;" : "=r"(r) : "f"(f));
    return r;
}
__device__ __forceinline__ float rnd_tf32(float f) { return __uint_as_float(cvt_tf32(f)); }

__device__ __forceinline__ void cpa16(uint32_t dst, const void* src) {
    asm volatile("cp.async.cg.shared.global [%0], [%1], 16;" :: "r"(dst), "l"(src));
}
#define CP_COMMIT() asm volatile("cp.async.commit_group;" ::: "memory")
#define CP_WAIT1()  asm volatile("cp.async.wait_group 1;" ::: "memory")

__device__ __forceinline__ void ldsm4(uint32_t* r, uint32_t addr) {
    asm volatile("ldmatrix.sync.aligned.m8n8.x4.shared.b16 {%0,%1,%2,%3}, [%4];"
        : "=r"(r[0]), "=r"(r[1]), "=r"(r[2]), "=r"(r[3]) : "r"(addr));
}

__device__ __forceinline__ void mma_tf32(float* c, const uint32_t* a, const uint32_t* b) {
    asm volatile(
        "mma.sync.aligned.m16n8k8.row.col.f32.tf32.tf32.f32 "
        "{%0,%1,%2,%3}, {%4,%5,%6,%7}, {%8,%9}, {%0,%1,%2,%3};\n"
        : "+f"(c[0]), "+f"(c[1]), "+f"(c[2]), "+f"(c[3])
        : "r"(a[0]), "r"(a[1]), "r"(a[2]), "r"(a[3]), "r"(b[0]), "r"(b[1]));
}

// ---------------- transpose + tf32-round ----------------
__global__ void trT_kernel(const float* __restrict__ src, float* __restrict__ dst,
                           int R, int C, long long dstZ)
{
    __shared__ float t[32][33];
    const int bx = blockIdx.x * 32;
    const int by = blockIdx.y * 32;
    const long long zs = (long long)blockIdx.z * R * C;
    const long long zd = (long long)blockIdx.z * dstZ;
    const int tx = threadIdx.x, ty = threadIdx.y;
#pragma unroll
    for (int j = 0; j < 32; j += 8)
        t[ty + j][tx] = src[zs + (long long)(by + ty + j) * C + bx + tx];
    __syncthreads();
#pragma unroll
    for (int j = 0; j < 32; j += 8)
        dst[zd + (long long)(bx + ty + j) * R + by + tx] = rnd_tf32(t[tx][ty + j]);
}

__global__ void bias_cat_kernel(const float* __restrict__ bq, const float* __restrict__ bk,
                                const float* __restrict__ bv, float* __restrict__ b)
{
    int i = blockIdx.x * 256 + threadIdx.x;
    b[i] = (i < 2048) ? bq[i] : (i < 4096 ? bk[i - 2048] : bv[i - 4096]);
}

// ---------------- tf32 mma.sync GEMM: 128x128 tile, BK=32, cp.async 3-stage ----------------
template <bool BNK>
__global__ __launch_bounds__(256, 2)
void mgemm_kernel(const float* __restrict__ A, const float* __restrict__ B,
                  float* __restrict__ C,
                  int M, int N, int K, int lda, int ldb, int ldc,
                  long long sAz, long long sBz, long long sCz,
                  const float* __restrict__ bias,
                  const float* __restrict__ residual, int ldr,
                  const int* __restrict__ a_rows, const int* __restrict__ a_cnt,
                  int causal, int roundOut, int perZ)
{
    const int mBase = blockIdx.y * 128;
    const int nBase = blockIdx.x * 128;
    if (causal == 1 && nBase >= mBase + 128) return;
    int count = M;
    if (a_cnt) {
        count = perZ ? a_cnt[blockIdx.z] : *a_cnt;
        if (count <= 0 || mBase >= count) return;
    }
    if (a_rows && perZ) a_rows += blockIdx.z * Sd;

    A += (long long)blockIdx.z * sAz;
    B += (long long)blockIdx.z * sBz;
    C += (long long)blockIdx.z * sCz;

    int kEnd = K;
    if (causal == 2) { int kl = mBase + 128; if (kl < kEnd) kEnd = kl; }
    const int nCh = kEnd >> 5;

    constexpr int ASZ = 128 * 36;
    constexpr int BSZ = BNK ? 128 * 36 : 32 * 136;
    constexpr int STG = ASZ + BSZ;

    extern __shared__ float sm[];
    const uint32_t smU = (uint32_t)__cvta_generic_to_shared(sm);

    const int tid  = threadIdx.x;
    const int lane = tid & 31;
    const int wid  = tid >> 5;
    const int wm   = (wid >> 2) * 64;
    const int wn   = (wid & 3) * 32;
    const int gr   = lane >> 2;
    const int tg   = lane & 3;

    const int ar0 = tid >> 3;
    const int ac  = (tid & 7) * 4;
    const float* aPtr[4];
#pragma unroll
    for (int j = 0; j < 4; j++) {
        int r = mBase + ar0 + 32 * j;
        if (a_rows) r = a_rows[r < count ? r : count - 1];
        aPtr[j] = A + (long long)r * lda + ac;
    }
    const float* bPtr[4];
    int br0 = 0, bc = 0;
    if (BNK) {
#pragma unroll
        for (int j = 0; j < 4; j++)
            bPtr[j] = B + (long long)(nBase + ar0 + 32 * j) * ldb + ac;
    } else {
        br0 = tid >> 5;
        bc  = (tid & 31) * 4;
#pragma unroll
        for (int j = 0; j < 4; j++)
            bPtr[j] = B + (long long)(br0 + 8 * j) * ldb + nBase + bc;
    }

    const uint32_t aOff = (uint32_t)((ar0 * 36 + ac) * 4);
    const uint32_t bOff = BNK ? aOff : (uint32_t)((br0 * 136 + bc) * 4);

    auto issue_chunk = [&](int c, int buf) {
        const int k0 = c << 5;
        const uint32_t base = smU + (uint32_t)(buf * STG * 4);
#pragma unroll
        for (int j = 0; j < 4; j++)
            cpa16(base + aOff + (uint32_t)(j * 32 * 36 * 4), aPtr[j] + k0);
        const uint32_t bbase = base + (uint32_t)(ASZ * 4);
        if (BNK) {
#pragma unroll
            for (int j = 0; j < 4; j++)
                cpa16(bbase + bOff + (uint32_t)(j * 32 * 36 * 4), bPtr[j] + k0);
        } else {
#pragma unroll
            for (int j = 0; j < 4; j++)
                cpa16(bbase + bOff + (uint32_t)(j * 8 * 136 * 4), bPtr[j] + (long long)k0 * ldb);
        }
    };

    const int t8 = lane & 7;
    const uint32_t aFrag = smU +
        (uint32_t)(((wm + ((lane >> 3) & 1) * 8 + t8) * 36 + (lane >> 4) * 4) * 4);
    const uint32_t bFrag = smU + (uint32_t)(ASZ * 4) +
        (uint32_t)(((wn + (lane >> 4) * 8 + t8) * 36 + ((lane >> 3) & 1) * 4) * 4);

    float acc[4][4][4];
#pragma unroll
    for (int mi = 0; mi < 4; mi++)
#pragma unroll
        for (int ni = 0; ni < 4; ni++)
#pragma unroll
            for (int e = 0; e < 4; e++) acc[mi][ni][e] = 0.f;

    issue_chunk(0, 0);
    CP_COMMIT();
    if (nCh > 1) issue_chunk(1, 1);
    CP_COMMIT();

    int buf = 0;
    for (int c = 0; c < nCh; c++) {
        CP_WAIT1();
        __syncthreads();

        const uint32_t bufB = (uint32_t)(buf * STG * 4);
        const float* Bs = sm + buf * STG + ASZ;

#pragma unroll
        for (int kk = 0; kk < 4; kk++) {
            const int ko = kk * 8;
            uint32_t af[4][4];
#pragma unroll
            for (int mi = 0; mi < 4; mi++)
                ldsm4(af[mi], aFrag + bufB + (uint32_t)((mi * 16 * 36 + ko) * 4));
            uint32_t bf[4][2];
            if (BNK) {
                uint32_t r4[4];
                ldsm4(r4, bFrag + bufB + (uint32_t)(ko * 4));
                bf[0][0] = r4[0]; bf[0][1] = r4[1]; bf[1][0] = r4[2]; bf[1][1] = r4[3];
                ldsm4(r4, bFrag + bufB + (uint32_t)((16 * 36 + ko) * 4));
                bf[2][0] = r4[0]; bf[2][1] = r4[1]; bf[3][0] = r4[2]; bf[3][1] = r4[3];
            } else {
#pragma unroll
                for (int ni = 0; ni < 4; ni++) {
                    const float* p = &Bs[(ko + tg) * 136 + wn + ni * 8 + gr];
                    bf[ni][0] = __float_as_uint(p[0]);
                    bf[ni][1] = __float_as_uint(p[4 * 136]);
                }
            }
#pragma unroll
            for (int mi = 0; mi < 4; mi++)
#pragma unroll
                for (int ni = 0; ni < 4; ni++)
                    mma_tf32(acc[mi][ni], af[mi], bf[ni]);
        }

        if (c + 2 < nCh) issue_chunk(c + 2, (buf + 2) % 3);
        CP_COMMIT();
        buf = (buf + 1) % 3;
    }

#pragma unroll
    for (int mi = 0; mi < 4; mi++) {
        const int gm0 = mBase + wm + mi * 16 + gr;
        const int gm1 = gm0 + 8;
        const bool ok0 = gm0 < count;
        const bool ok1 = gm1 < count;
#pragma unroll
        for (int ni = 0; ni < 4; ni++) {
            const int gn = nBase + wn + ni * 8 + tg * 2;
            float2 v0 = make_float2(acc[mi][ni][0], acc[mi][ni][1]);
            float2 v1 = make_float2(acc[mi][ni][2], acc[mi][ni][3]);
            if (bias) {
                float2 b = *(const float2*)(bias + gn);
                v0.x += b.x; v0.y += b.y; v1.x += b.x; v1.y += b.y;
            }
            if (roundOut) {
                v0.x = rnd_tf32(v0.x); v0.y = rnd_tf32(v0.y);
                v1.x = rnd_tf32(v1.x); v1.y = rnd_tf32(v1.y);
            }
            if (ok0) {
                if (residual) {
                    float2 r = *(const float2*)(residual + (long long)gm0 * ldr + gn);
                    v0.x += r.x; v0.y += r.y;
                }
                *(float2*)(C + (long long)gm0 * ldc + gn) = v0;
            }
            if (ok1) {
                if (residual) {
                    float2 r = *(const float2*)(residual + (long long)gm1 * ldr + gn);
                    v1.x += r.x; v1.y += r.y;
                }
                *(float2*)(C + (long long)gm1 * ldc + gn) = v1;
            }
        }
    }
}

// ---------------- flash attention: 128 queries x 64-key blocks, tf32 mma ----------------
// grid (16 mb, 16 heads); CTA 256 threads, 8 warps: S warp tile 64x16 (2m x 4n),
// PV/O warp tile 64x32. Q resident in smem; K/V single-buffered with staggered
// cp.async groups; S staged in smem for softmax + P ldsm reload; O in registers.
__global__ __launch_bounds__(256, 1)
void flash_kernel(const float* __restrict__ qkv, float* __restrict__ attn)
{
    const int mb   = (int)gridDim.x - 1 - (int)blockIdx.x;   // longest-job-first
    const int head = blockIdx.y;
    const int mBase = mb * 128;
    const int nKb = 2 * mb + 2;

    extern __shared__ float sm[];
    float* Qs  = sm;                    // [128][132]
    float* Ks  = Qs + 128 * 132;        // [64][132]
    float* Vs  = Ks + 64 * 132;         // [64][132]
    float* Ss  = Vs + 64 * 132;         // [128][68]
    float* m_s = Ss + 128 * 68;         // [128]
    float* l_s = m_s + 128;             // [128]
    float* f_s = l_s + 128;             // [128]
    const uint32_t QsU = (uint32_t)__cvta_generic_to_shared(Qs);
    const uint32_t KsU = (uint32_t)__cvta_generic_to_shared(Ks);
    const uint32_t VsU = (uint32_t)__cvta_generic_to_shared(Vs);
    const uint32_t SsU = (uint32_t)__cvta_generic_to_shared(Ss);

    const int tid  = threadIdx.x;
    const int lane = tid & 31;
    const int wid  = tid >> 5;
    const int gr   = lane >> 2;
    const int tg   = lane & 3;
    const int t8   = lane & 7;
    const int wm   = (wid >> 2) * 64;     // S/O rows
    const int wnS  = (wid & 3) * 16;      // S cols (64 total)
    const int wnO  = (wid & 3) * 32;      // O cols (128 total)

    // loaders
    const int qr = tid >> 1, qc = (tid & 1) * 64;
    const float* qsrc = qkv + (long long)(mBase + qr) * QKVW + head * 128 + qc;
    const uint32_t qdst = QsU + (uint32_t)((qr * 132 + qc) * 4);
    const int kr = tid >> 2, kc = (tid & 3) * 32;
    const uint32_t kdst = KsU + (uint32_t)((kr * 132 + kc) * 4);
    const uint32_t vdst = VsU + (uint32_t)((kr * 132 + kc) * 4);

    auto loadK = [&](int kb) {
        const float* src = qkv + (long long)(kb * 64 + kr) * QKVW + 2048 + head * 128 + kc;
#pragma unroll
        for (int u = 0; u < 8; u++) cpa16(kdst + u * 16, src + u * 4);
    };
    auto loadV = [&](int kb) {
        const float* src = qkv + (long long)(kb * 64 + kr) * QKVW + 4096 + head * 128 + kc;
#pragma unroll
        for (int u = 0; u < 8; u++) cpa16(vdst + u * 16, src + u * 4);
    };

    // prologue: Q + K0 (group0), V0 (group1)
#pragma unroll
    for (int u = 0; u < 16; u++) cpa16(qdst + u * 16, qsrc + u * 4);
    loadK(0);
    CP_COMMIT();
    loadV(0);
    CP_COMMIT();

    if (tid < 128) { m_s[tid] = -1e30f; l_s[tid] = 0.f; }

    // fragment bases
    const uint32_t aQbase = QsU + (uint32_t)(((wm + ((lane >> 3) & 1) * 8 + t8) * 132 + (lane >> 4) * 4) * 4);
    const uint32_t bKbase = KsU + (uint32_t)(((wnS + (lane >> 4) * 8 + t8) * 132 + ((lane >> 3) & 1) * 4) * 4);
    const uint32_t aPbase = SsU + (uint32_t)(((wm + ((lane >> 3) & 1) * 8 + t8) * 68 + (lane >> 4) * 4) * 4);

    float O[4][4][4];
#pragma unroll
    for (int mi = 0; mi < 4; mi++)
#pragma unroll
        for (int ni = 0; ni < 4; ni++)
#pragma unroll
            for (int e = 0; e < 4; e++) O[mi][ni][e] = 0.f;

    const float scale = 0.08838834764831845f;

    for (int kb = 0; kb < nKb; kb++) {
        CP_WAIT1();              // Q+K(kb) arrived
        __syncthreads();

        // ---- S = Q @ K^T (K-dim = d = 128) ----
        float Sacc[4][2][4];
#pragma unroll
        for (int mi = 0; mi < 4; mi++)
#pragma unroll
            for (int ni = 0; ni < 2; ni++)
#pragma unroll
                for (int e = 0; e < 4; e++) Sacc[mi][ni][e] = 0.f;

#pragma unroll
        for (int kk = 0; kk < 16; kk++) {
            uint32_t af[4][4];
#pragma unroll
            for (int mi = 0; mi < 4; mi++)
                ldsm4(af[mi], aQbase + (uint32_t)((mi * 16 * 132 + kk * 8) * 4));
            uint32_t r4[4];
            ldsm4(r4, bKbase + (uint32_t)(kk * 32));
            uint32_t bf[2][2];
            bf[0][0] = r4[0]; bf[0][1] = r4[1]; bf[1][0] = r4[2]; bf[1][1] = r4[3];
#pragma unroll
            for (int mi = 0; mi < 4; mi++)
#pragma unroll
                for (int ni = 0; ni < 2; ni++)
                    mma_tf32(Sacc[mi][ni], af[mi], bf[ni]);
        }

        // ---- store S (scaled + causal-masked) ----
#pragma unroll
        for (int mi = 0; mi < 4; mi++) {
            const int r0 = wm + mi * 16 + gr;
            const int r1 = r0 + 8;
#pragma unroll
            for (int ni = 0; ni < 2; ni++) {
                const int c = wnS + ni * 8 + tg * 2;
                const int key = kb * 64 + c;
                float2 v0, v1;
                v0.x = (key     > mBase + r0) ? -1e30f : Sacc[mi][ni][0] * scale;
                v0.y = (key + 1 > mBase + r0) ? -1e30f : Sacc[mi][ni][1] * scale;
                v1.x = (key     > mBase + r1) ? -1e30f : Sacc[mi][ni][2] * scale;
                v1.y = (key + 1 > mBase + r1) ? -1e30f : Sacc[mi][ni][3] * scale;
                *(float2*)&Ss[r0 * 68 + c] = v0;
                *(float2*)&Ss[r1 * 68 + c] = v1;
            }
        }
        __syncthreads();         // K fully consumed, S visible

        if (kb + 1 < nKb) loadK(kb + 1);
        CP_COMMIT();

        // ---- online softmax over this 64-key block ----
        {
            const int r = tid >> 1, half = tid & 1;
            float* row = &Ss[r * 68 + half * 32];
            float4 v[8];
            float mx = -1e30f;
#pragma unroll
            for (int u = 0; u < 8; u++) {
                v[u] = *(float4*)&row[u * 4];
                mx = fmaxf(mx, fmaxf(fmaxf(v[u].x, v[u].y), fmaxf(v[u].z, v[u].w)));
            }
            mx = fmaxf(mx, __shfl_xor_sync(0xffffffffu, mx, 1));
            const float mo = m_s[r];
            const float nm = fmaxf(mo, mx);
            float ls = 0.f;
#pragma unroll
            for (int u = 0; u < 8; u++) {
                v[u].x = __expf(v[u].x - nm); v[u].y = __expf(v[u].y - nm);
                v[u].z = __expf(v[u].z - nm); v[u].w = __expf(v[u].w - nm);
                ls += v[u].x + v[u].y + v[u].z + v[u].w;
                v[u].x = rnd_tf32(v[u].x); v[u].y = rnd_tf32(v[u].y);
                v[u].z = rnd_tf32(v[u].z); v[u].w = rnd_tf32(v[u].w);
                *(float4*)&row[u * 4] = v[u];
            }
            ls += __shfl_xor_sync(0xffffffffu, ls, 1);
            if (half == 0) {
                const float f = __expf(mo - nm);
                l_s[r] = l_s[r] * f + ls;
                m_s[r] = nm;
                f_s[r] = f;
            }
        }
        __syncthreads();         // P, f_s ready

        CP_WAIT1();              // V(kb) arrived

        // ---- rescale O, then O += P @ V (K-dim = 64 keys) ----
#pragma unroll
        for (int mi = 0; mi < 4; mi++) {
            const float f0 = f_s[wm + mi * 16 + gr];
            const float f1 = f_s[wm + mi * 16 + gr + 8];
#pragma unroll
            for (int ni = 0; ni < 4; ni++) {
                O[mi][ni][0] *= f0; O[mi][ni][1] *= f0;
                O[mi][ni][2] *= f1; O[mi][ni][3] *= f1;
            }
        }
#pragma unroll
        for (int kk = 0; kk < 8; kk++) {
            uint32_t af[4][4];
#pragma unroll
            for (int mi = 0; mi < 4; mi++)
                ldsm4(af[mi], aPbase + (uint32_t)((mi * 16 * 68 + kk * 8) * 4));
            uint32_t bf[4][2];
#pragma unroll
            for (int ni = 0; ni < 4; ni++) {
                const float* p = &Vs[(kk * 8 + tg) * 132 + wnO + ni * 8 + gr];
                bf[ni][0] = __float_as_uint(p[0]);
                bf[ni][1] = __float_as_uint(p[4 * 132]);
            }
#pragma unroll
            for (int mi = 0; mi < 4; mi++)
#pragma unroll
                for (int ni = 0; ni < 4; ni++)
                    mma_tf32(O[mi][ni], af[mi], bf[ni]);
        }
        __syncthreads();         // V fully consumed

        if (kb + 1 < nKb) loadV(kb + 1);
        CP_COMMIT();
    }

    // ---- epilogue: O / l, rounded, to attn ----
#pragma unroll
    for (int mi = 0; mi < 4; mi++) {
        const int r0 = wm + mi * 16 + gr;
        const int r1 = r0 + 8;
        const float il0 = 1.0f / l_s[r0];
        const float il1 = 1.0f / l_s[r1];
        float* o0 = attn + (long long)(mBase + r0) * Hd + head * 128;
        float* o1 = attn + (long long)(mBase + r1) * Hd + head * 128;
#pragma unroll
        for (int ni = 0; ni < 4; ni++) {
            const int c = wnO + ni * 8 + tg * 2;
            float2 v0 = make_float2(rnd_tf32(O[mi][ni][0] * il0), rnd_tf32(O[mi][ni][1] * il0));
            float2 v1 = make_float2(rnd_tf32(O[mi][ni][2] * il1), rnd_tf32(O[mi][ni][3] * il1));
            *(float2*)(o0 + c) = v0;
            *(float2*)(o1 + c) = v1;
        }
    }
}

// ---------------- elementwise / reduction kernels ----------------
__global__ void reset_cnt_kernel(int* cnt)
{
    if (threadIdx.x < Ed) cnt[threadIdx.x] = 0;
}

__global__ void rmsnorm_kernel(const float* __restrict__ x, const float* __restrict__ w,
                               float* __restrict__ y, float* __restrict__ y2)
{
    int s = blockIdx.x, tid = threadIdx.x;
    __shared__ float red[256];
    __shared__ float srs;
    const float* xr = x + (long long)s * Hd;
    float sum = 0.f;
    for (int h = tid; h < Hd; h += 256) { float v = xr[h]; sum += v * v; }
    red[tid] = sum; __syncthreads();
    for (int st = 128; st > 0; st >>= 1) {
        if (tid < st) red[tid] += red[tid + st];
        __syncthreads();
    }
    if (tid == 0) srs = rsqrtf(red[0] / (float)Hd + 1e-6f);
    __syncthreads();
    float rs = srs;
    float* yr = y + (long long)s * Hd;
    float* y2r = y2 ? y2 + (long long)s * Hd : nullptr;
    for (int h = tid; h < Hd; h += 256) {
        float v = w[h] * xr[h] * rs;
        yr[h] = rnd_tf32(v);
        if (y2r) y2r[h] = v;
    }
}

__global__ void rope_kernel(float* __restrict__ qkv)
{
    int i = blockIdx.x * 256 + threadIdx.x;
    int hi = i & 63;
    int h  = (i >> 6) & 15;
    int s  = i >> 10;
    float inv = powf(1000000.0f, -(float)hi / 64.0f);
    float ang = (float)s * inv;
    float sv, cv; sincosf(ang, &sv, &cv);
    long long base = (long long)s * QKVW + h * Dd + hi;
    float q1 = qkv[base], q2 = qkv[base + 64];
    qkv[base]      = rnd_tf32(q1 * cv - q2 * sv);
    qkv[base + 64] = rnd_tf32(q2 * cv + q1 * sv);
    float k1 = qkv[base + 2048], k2 = qkv[base + 2048 + 64];
    qkv[base + 2048]      = rnd_tf32(k1 * cv - k2 * sv);
    qkv[base + 2048 + 64] = rnd_tf32(k2 * cv + k1 * sv);
}

__global__ void router_kernel(const float* __restrict__ h2, const float* __restrict__ gate_w,
                              float* __restrict__ logits_out,
                              float* __restrict__ w4, int* __restrict__ sel4, int* __restrict__ pos4,
                              int* __restrict__ cnt, int* __restrict__ idx)
{
    int s = blockIdx.x, tid = threadIdx.x;
    __shared__ float red[256][8];
    float loc[8];
#pragma unroll
    for (int e = 0; e < 8; e++) loc[e] = 0.f;
    const float* hr = h2 + (long long)s * Hd;
    for (int h = tid; h < Hd; h += 256) {
        float hv = hr[h];
#pragma unroll
        for (int e = 0; e < 8; e++) loc[e] += hv * gate_w[h * 8 + e];
    }
#pragma unroll
    for (int e = 0; e < 8; e++) red[tid][e] = loc[e];
    __syncthreads();
    for (int st = 128; st > 0; st >>= 1) {
        if (tid < st) {
#pragma unroll
            for (int e = 0; e < 8; e++) red[tid][e] += red[tid + st][e];
        }
        __syncthreads();
    }
    if (tid == 0) {
        float l[8], p[8];
        float mx = -3.4e38f;
#pragma unroll
        for (int e = 0; e < 8; e++) { l[e] = red[0][e]; logits_out[s * 8 + e] = l[e]; mx = fmaxf(mx, l[e]); }
        float sum = 0.f;
#pragma unroll
        for (int e = 0; e < 8; e++) { p[e] = expf(l[e] - mx); sum += p[e]; }
#pragma unroll
        for (int e = 0; e < 8; e++) p[e] /= sum;
        bool used[8] = {false, false, false, false, false, false, false, false};
        for (int t = 0; t < 4; t++) {
            int best = -1; float bv = -1.f;
            for (int e = 0; e < 8; e++)
                if (!used[e] && p[e] > bv) { bv = p[e]; best = e; }
            used[best] = true;
            int pos = atomicAdd(&cnt[best], 1);
            idx[best * Sd + pos] = s;
            w4[s * 4 + t] = bv;
            sel4[s * 4 + t] = best;
            pos4[s * 4 + t] = pos;
        }
    }
}

__global__ void silu_gu_kernel(float* __restrict__ GU, const int* __restrict__ cnt)
{
    long long i = (long long)blockIdx.x * 256 + threadIdx.x;
    int col = (int)(i % IEd);
    int row = (int)((i / IEd) & 2047);
    int e   = (int)(i / ((long long)Sd * IEd));
    if (row >= cnt[e]) return;
    long long base = ((long long)e * Sd + row) * GUW;
    float g = GU[base + col], u = GU[base + IEd + col];
    GU[base + col] = rnd_tf32((g / (1.f + expf(-g))) * u);
}

__global__ void silu_sh_kernel(float* __restrict__ SGU)
{
    long long i = (long long)blockIdx.x * 256 + threadIdx.x;
    int col = (int)(i % ISd);
    int row = (int)(i / ISd);
    long long base = (long long)row * SGW;
    float g = SGU[base + col], u = SGU[base + ISd + col];
    SGU[base + col] = rnd_tf32((g / (1.f + expf(-g))) * u);
}

__global__ void sgate_kernel(const float* __restrict__ h2, const float* __restrict__ sgate,
                             float* __restrict__ sig)
{
    int s = blockIdx.x, tid = threadIdx.x;
    __shared__ float red[256];
    const float* hr = h2 + (long long)s * Hd;
    float sum = 0.f;
    for (int h = tid; h < Hd; h += 256) sum += hr[h] * sgate[h];
    red[tid] = sum; __syncthreads();
    for (int st = 128; st > 0; st >>= 1) {
        if (tid < st) red[tid] += red[tid + st];
        __syncthreads();
    }
    if (tid == 0) sig[s] = 1.f / (1.f + expf(-red[0]));
}

__global__ void combine_kernel(float* __restrict__ out, const float* __restrict__ Ye,
                               const float* __restrict__ Ysh,
                               const float* __restrict__ w4, const int* __restrict__ sel4,
                               const int* __restrict__ pos4, const float* __restrict__ sig)
{
    int i = blockIdx.x * 256 + threadIdx.x;
    int s = i >> 11, c = i & 2047;
    float acc = out[i];
#pragma unroll
    for (int t = 0; t < 4; t++) {
        int e = sel4[s * 4 + t];
        int p = pos4[s * 4 + t];
        acc += w4[s * 4 + t] * Ye[((long long)e * Sd + p) * Hd + c];
    }
    out[i] = acc + sig[s] * Ysh[i];
}

// ---------------- host-side dispatch ----------------
static const int SMEM_T = 3 * (128 * 36 + 128 * 36) * 4;   // 110592
static const int SMEM_F = 3 * (128 * 36 + 32 * 136) * 4;   // 107520
static const int SMEM_FLASH = (128 * 132 + 64 * 132 * 2 + 128 * 68 + 384) * 4;  // 171520

static inline void tgemm(bool bnk, const float* A, const float* B, float* C,
                         int M, int N, int K, int lda, int ldb, int ldc,
                         long long sA = 0, long long sB = 0, long long sC = 0, int nz = 1,
                         const float* bias = nullptr,
                         const float* residual = nullptr, int ldr = 0,
                         const int* arows = nullptr, const int* acnt = nullptr,
                         int causal = 0, int roundOut = 0, int perZ = 0)
{
    dim3 grid(N / 128, (M + 127) / 128, nz);
    if (bnk)
        mgemm_kernel<true><<<grid, 256, SMEM_T>>>(A, B, C, M, N, K, lda, ldb, ldc,
                                                  sA, sB, sC, bias, residual, ldr, arows, acnt,
                                                  causal, roundOut, perZ);
    else
        mgemm_kernel<false><<<grid, 256, SMEM_F>>>(A, B, C, M, N, K, lda, ldb, ldc,
                                                   sA, sB, sC, bias, residual, ldr, arows, acnt,
                                                   causal, roundOut, perZ);
}

static inline void trT(const float* src, float* dst, int R, int C, int nz, long long dstZ)
{
    dim3 grid(C / 32, R / 32, nz);
    trT_kernel<<<grid, dim3(32, 8)>>>(src, dst, R, C, dstZ);
}

extern "C" void kernel_launch(void* const* d_in, const int* in_sizes, int n_in,
                              void* d_out, int out_size)
{
    cudaFuncSetAttribute(mgemm_kernel<true>,  cudaFuncAttributeMaxDynamicSharedMemorySize, SMEM_T);
    cudaFuncSetAttribute(mgemm_kernel<false>, cudaFuncAttributeMaxDynamicSharedMemorySize, SMEM_F);
    cudaFuncSetAttribute(flash_kernel, cudaFuncAttributeMaxDynamicSharedMemorySize, SMEM_FLASH);

    const float* x     = (const float*)d_in[0];
    const float* ln1   = (const float*)d_in[1];
    const float* ln2   = (const float*)d_in[2];
    const float* wq    = (const float*)d_in[3];
    const float* bq    = (const float*)d_in[4];
    const float* wk    = (const float*)d_in[5];
    const float* bk    = (const float*)d_in[6];
    const float* wv    = (const float*)d_in[7];
    const float* bv    = (const float*)d_in[8];
    const float* wo    = (const float*)d_in[9];
    const float* gate  = (const float*)d_in[10];
    const float* eg    = (const float*)d_in[11];
    const float* eu    = (const float*)d_in[12];
    const float* ed    = (const float*)d_in[13];
    const float* sg    = (const float*)d_in[14];
    const float* su    = (const float*)d_in[15];
    const float* sd    = (const float*)d_in[16];
    const float* sgate = (const float*)d_in[17];

    float* out        = (float*)d_out;
    float* out_x      = out;
    float* out_logits = out + (long long)Sd * Hd;

    float *h1, *qkv, *attn, *h2, *h2x, *GU, *Ye, *SGU, *Ysh, *sig, *w4, *bqkv;
    float *qkvT, *woT, *guT, *edT, *sguT, *sdT;
    int *cnt, *idx, *sel4, *pos4;
    cudaGetSymbolAddress((void**)&h1,     g_h1);
    cudaGetSymbolAddress((void**)&qkv,    g_qkv);
    cudaGetSymbolAddress((void**)&attn,   g_attn);
    cudaGetSymbolAddress((void**)&h2,     g_h2);
    cudaGetSymbolAddress((void**)&h2x,    g_h2x);
    cudaGetSymbolAddress((void**)&GU,     g_GU);
    cudaGetSymbolAddress((void**)&Ye,     g_Ye);
    cudaGetSymbolAddress((void**)&SGU,    g_SGU);
    cudaGetSymbolAddress((void**)&Ysh,    g_Ysh);
    cudaGetSymbolAddress((void**)&sig,    g_sig);
    cudaGetSymbolAddress((void**)&w4,     g_w4);
    cudaGetSymbolAddress((void**)&bqkv,   g_bqkv);
    cudaGetSymbolAddress((void**)&cnt,    g_cnt);
    cudaGetSymbolAddress((void**)&idx,    g_idx);
    cudaGetSymbolAddress((void**)&sel4,   g_sel4);
    cudaGetSymbolAddress((void**)&pos4,   g_pos4);
    cudaGetSymbolAddress((void**)&qkvT,   g_qkvT);
    cudaGetSymbolAddress((void**)&woT,    g_woT);
    cudaGetSymbolAddress((void**)&guT,    g_guT);
    cudaGetSymbolAddress((void**)&edT,    g_edT);
    cudaGetSymbolAddress((void**)&sguT,   g_sguT);
    cudaGetSymbolAddress((void**)&sdT,    g_sdT);

    // 0. weight transposes (+tf32 rounding), fused layouts
    trT(wq, qkvT,                          Hd, Hd, 1, 0);
    trT(wk, qkvT + (long long)Hd * Hd,     Hd, Hd, 1, 0);
    trT(wv, qkvT + (long long)2 * Hd * Hd, Hd, Hd, 1, 0);
    trT(wo, woT, Hd, Hd, 1, 0);
    trT(eg, guT,                           Hd, IEd, Ed, (long long)GUW * Hd);
    trT(eu, guT + (long long)IEd * Hd,     Hd, IEd, Ed, (long long)GUW * Hd);
    trT(ed, edT, IEd, Hd, Ed, (long long)Hd * IEd);
    trT(sg, sguT,                          Hd, ISd, 1, 0);
    trT(su, sguT + (long long)ISd * Hd,    Hd, ISd, 1, 0);
    trT(sd, sdT, ISd, Hd, 1, 0);
    bias_cat_kernel<<<QKVW / 256, 256>>>(bq, bk, bv, bqkv);
    reset_cnt_kernel<<<1, 32>>>(cnt);

    // 1. rmsnorm -> h1
    rmsnorm_kernel<<<Sd, 256>>>(x, ln1, h1, nullptr);

    // 2. fused QKV projection (+bias, rounded)
    tgemm(true, h1, qkvT, qkv, Sd, QKVW, Hd, Hd, Hd, QKVW, 0, 0, 0, 1, bqkv,
          nullptr, 0, nullptr, nullptr, 0, 1);

    // 3. RoPE
    rope_kernel<<<(Sd * NHd * 64) / 256, 256>>>(qkv);

    // 4-6. fused flash attention (rounded output)
    flash_kernel<<<dim3(16, 16), 256, SMEM_FLASH>>>(qkv, attn);

    // 7. x2 = x + attn @ wo
    tgemm(true, attn, woT, out_x, Sd, Hd, Hd, Hd, Hd, Hd, 0, 0, 0, 1, nullptr, x, Hd);

    // 8. rmsnorm -> h2 (+ exact h2x)
    rmsnorm_kernel<<<Sd, 256>>>(out_x, ln2, h2, h2x);

    // 9. router
    router_kernel<<<Sd, 256>>>(h2x, gate, out_logits, w4, sel4, pos4, cnt, idx);

    // 10. routed MoE — batched across experts (z=8), fused G|U
    tgemm(true, h2, guT, GU, Sd, GUW, Hd, Hd, Hd, GUW,
          0, (long long)GUW * Hd, (long long)Sd * GUW, Ed,
          nullptr, nullptr, 0, idx, cnt, 0, 0, 1);
    silu_gu_kernel<<<(int)(((long long)Ed * Sd * IEd) / 256), 256>>>(GU, cnt);
    tgemm(true, GU, edT, Ye, Sd, Hd, IEd, GUW, IEd, Hd,
          (long long)Sd * GUW, (long long)Hd * IEd, (long long)Sd * Hd, Ed,
          nullptr, nullptr, 0, nullptr, cnt, 0, 0, 1);

    // 11. shared expert — fused sg|su
    tgemm(true, h2, sguT, SGU, Sd, SGW, Hd, Hd, Hd, SGW);
    silu_sh_kernel<<<(int)(((long long)Sd * ISd) / 256), 256>>>(SGU);
    tgemm(true, SGU, sdT, Ysh, Sd, Hd, ISd, SGW, ISd, Hd);
    sgate_kernel<<<Sd, 256>>>(h2x, sgate, sig);

    // 12. deterministic fused combine (MoE + shared)
    combine_kernel<<<(Sd * Hd) / 256, 256>>>(out_x, Ye, Ysh, w4, sel4, pos4, sig);

    (void)in_sizes; (void)n_in; (void)out_size;
}